// round 1
// baseline (speedup 1.0000x reference)
#include <cuda_runtime.h>
#include <math.h>

#define NN 4096
#define MEM 512

// ---------------- scratch (static device globals; no allocation) ----------------
__device__ float g_ifou[NN * 2048];          // inputs @ Wx + bx   (32 MB)
__device__ float g_c[(NN + 1) * MEM];        // cell states, row NN = sentinel zeros
__device__ float g_h[(NN + 1) * MEM];        // hidden states, row NN = sentinel zeros
__device__ float g_iou[683 * 1536];          // per-level hsum @ Ws + bs
__device__ float g_f[2732 * 512];            // per-level child_h @ Wf + bf

__device__ __forceinline__ float sigmoidf_(float x) { return 1.0f / (1.0f + expf(-x)); }

// children of node p are ids 4p-12289 .. 4p-12286 (clip <0 -> sentinel NN)
__device__ __forceinline__ int child_id(int p, int k) {
    int c = 4 * p - 12289 + k;
    return c < 0 ? NN : c;
}

// ---------------- generic fp32 GEMM, C[M,Ncol] = A[M,512] @ B[512,Ncol] + bias ----
// MODE 0: A is a dense row-major array (pointer A)
// MODE 1: A row m = sum of the 4 child h-rows of node (base+m)        (hsum @ Ws)
// MODE 2: A row r = h-row of child (r%4) of node (base + r/4)        (child h @ Wf)
template <int MODE>
__device__ __forceinline__ float4 load_a(const float* __restrict__ A,
                                         const float* __restrict__ H,
                                         int row, int kcol, int M, int base) {
    float4 z = make_float4(0.f, 0.f, 0.f, 0.f);
    if (row >= M) return z;
    if (MODE == 0) {
        return *reinterpret_cast<const float4*>(A + (size_t)row * 512 + kcol);
    } else if (MODE == 1) {
        int p = base + row;
        float4 s = z;
#pragma unroll
        for (int k = 0; k < 4; ++k) {
            int cid = child_id(p, k);
            float4 v = *reinterpret_cast<const float4*>(H + (size_t)cid * 512 + kcol);
            s.x += v.x; s.y += v.y; s.z += v.z; s.w += v.w;
        }
        return s;
    } else {
        int p = base + (row >> 2);
        int cid = child_id(p, row & 3);
        return *reinterpret_cast<const float4*>(H + (size_t)cid * 512 + kcol);
    }
}

constexpr int BM = 128, BN = 128, BK = 8;

template <int MODE>
__global__ __launch_bounds__(256)
void gemm_kernel(const float* __restrict__ A, const float* __restrict__ B,
                 const float* __restrict__ bias, float* __restrict__ C,
                 const float* __restrict__ H, int M, int Ncol, int base) {
    __shared__ float As[BK][BM];
    __shared__ float Bs[BK][BN];
    const int tid = threadIdx.x;
    const int bm = blockIdx.y * BM;
    const int bn = blockIdx.x * BN;
    const int tx = tid & 15;          // 16 cols of 8
    const int ty = tid >> 4;          // 16 rows of 8

    float acc[8][8];
#pragma unroll
    for (int i = 0; i < 8; ++i)
#pragma unroll
        for (int j = 0; j < 8; ++j) acc[i][j] = 0.f;

    const int arow = tid >> 1;            // 0..127
    const int akp = (tid & 1) * 4;        // 0 or 4
    const int bcol = (tid & 31) * 4;      // 0..124
    const int bkrow = tid >> 5;           // 0..7

    for (int k0 = 0; k0 < 512; k0 += BK) {
        float4 av = load_a<MODE>(A, H, bm + arow, k0 + akp, M, base);
        float4 bv = *reinterpret_cast<const float4*>(B + (size_t)(k0 + bkrow) * Ncol + bn + bcol);
        __syncthreads();
        As[akp + 0][arow] = av.x;
        As[akp + 1][arow] = av.y;
        As[akp + 2][arow] = av.z;
        As[akp + 3][arow] = av.w;
        *reinterpret_cast<float4*>(&Bs[bkrow][bcol]) = bv;
        __syncthreads();
#pragma unroll
        for (int kk = 0; kk < BK; ++kk) {
            float a[8], b[8];
            *reinterpret_cast<float4*>(&a[0]) = *reinterpret_cast<const float4*>(&As[kk][ty * 8]);
            *reinterpret_cast<float4*>(&a[4]) = *reinterpret_cast<const float4*>(&As[kk][ty * 8 + 4]);
            *reinterpret_cast<float4*>(&b[0]) = *reinterpret_cast<const float4*>(&Bs[kk][tx * 8]);
            *reinterpret_cast<float4*>(&b[4]) = *reinterpret_cast<const float4*>(&Bs[kk][tx * 8 + 4]);
#pragma unroll
            for (int i = 0; i < 8; ++i)
#pragma unroll
                for (int j = 0; j < 8; ++j) acc[i][j] = fmaf(a[i], b[j], acc[i][j]);
        }
    }

#pragma unroll
    for (int i = 0; i < 8; ++i) {
        int row = bm + ty * 8 + i;
        if (row < M) {
            int col = bn + tx * 8;
            float4 o0, o1;
            o0.x = acc[i][0] + bias[col + 0];
            o0.y = acc[i][1] + bias[col + 1];
            o0.z = acc[i][2] + bias[col + 2];
            o0.w = acc[i][3] + bias[col + 3];
            o1.x = acc[i][4] + bias[col + 4];
            o1.y = acc[i][5] + bias[col + 5];
            o1.z = acc[i][6] + bias[col + 6];
            o1.w = acc[i][7] + bias[col + 7];
            *reinterpret_cast<float4*>(&C[(size_t)row * Ncol + col]) = o0;
            *reinterpret_cast<float4*>(&C[(size_t)row * Ncol + col + 4]) = o1;
        }
    }
}

// ---------------- elementwise kernels ----------------
__global__ void init_kernel(float* cbuf, float* hbuf) {
    int j = threadIdx.x;
    cbuf[(size_t)NN * MEM + j] = 0.f;
    hbuf[(size_t)NN * MEM + j] = 0.f;
}

// leaves: ids 0..3071, no children -> iou = bs, c = i*u
__global__ void leaf_kernel(const float* __restrict__ ifou, const float* __restrict__ bs,
                            float* __restrict__ cbuf, float* __restrict__ hbuf) {
    int p = blockIdx.x;
    int j = threadIdx.x;
    const float* r = ifou + (size_t)p * 2048;
    float iv = sigmoidf_(r[j] + bs[j]);
    float ov = sigmoidf_(r[1024 + j] + bs[512 + j]);
    float uv = tanhf(r[1536 + j] + bs[1024 + j]);
    float c = iv * uv;
    cbuf[(size_t)p * MEM + j] = c;
    hbuf[(size_t)p * MEM + j] = ov * tanhf(c);
}

__global__ void combine_kernel(const float* __restrict__ ifou, const float* __restrict__ iou,
                               const float* __restrict__ fraw, float* __restrict__ cbuf,
                               float* __restrict__ hbuf, int base) {
    int m = blockIdx.x;
    int j = threadIdx.x;
    int p = base + m;
    const float* r = ifou + (size_t)p * 2048;
    float ix = r[j], fx = r[512 + j], ox = r[1024 + j], ux = r[1536 + j];
    float iv = sigmoidf_(ix + iou[(size_t)m * 1536 + j]);
    float ov = sigmoidf_(ox + iou[(size_t)m * 1536 + 512 + j]);
    float uv = tanhf(ux + iou[(size_t)m * 1536 + 1024 + j]);
    float c = iv * uv;
#pragma unroll
    for (int k = 0; k < 4; ++k) {
        int cid = child_id(p, k);
        float f = sigmoidf_(fraw[((size_t)m * 4 + k) * 512 + j] + fx);
        c += f * cbuf[(size_t)cid * MEM + j];
    }
    cbuf[(size_t)p * MEM + j] = c;
    hbuf[(size_t)p * MEM + j] = ov * tanhf(c);
}

__global__ void copyout_kernel(const float* __restrict__ hbuf, float* __restrict__ out) {
    out[threadIdx.x] = hbuf[(size_t)(NN - 1) * MEM + threadIdx.x];
}

// ---------------- launch ----------------
extern "C" void kernel_launch(void* const* d_in, const int* in_sizes, int n_in,
                              void* d_out, int out_size) {
    const float* inputs = (const float*)d_in[0];   // [4096, 512]
    const float* Wx     = (const float*)d_in[1];   // [512, 2048]
    const float* bx     = (const float*)d_in[2];   // [2048]
    const float* Ws     = (const float*)d_in[3];   // [512, 1536]
    const float* bs     = (const float*)d_in[4];   // [1536]
    const float* Wf     = (const float*)d_in[5];   // [512, 512]
    const float* bf     = (const float*)d_in[6];   // [512]
    float* out = (float*)d_out;                    // [512]

    float *ifou, *cbuf, *hbuf, *iou, *fraw;
    cudaGetSymbolAddress((void**)&ifou, g_ifou);
    cudaGetSymbolAddress((void**)&cbuf, g_c);
    cudaGetSymbolAddress((void**)&hbuf, g_h);
    cudaGetSymbolAddress((void**)&iou, g_iou);
    cudaGetSymbolAddress((void**)&fraw, g_f);

    init_kernel<<<1, 512>>>(cbuf, hbuf);

    // ifou = inputs @ Wx + bx  for all nodes
    gemm_kernel<0><<<dim3(2048 / BN, NN / BM), 256>>>(inputs, Wx, bx, ifou, nullptr, NN, 2048, 0);

    // leaves (ids 0..3071): pure elementwise
    leaf_kernel<<<3072, 512>>>(ifou, bs, cbuf, hbuf);

    // internal levels bottom-up
    static const int baseArr[6] = {3072, 3755, 4011, 4075, 4091, 4095};
    static const int cntArr[6]  = {683, 256, 64, 16, 4, 1};
    for (int l = 0; l < 6; ++l) {
        int m = cntArr[l], base = baseArr[l];
        // hsum @ Ws + bs  -> [m, 1536]
        gemm_kernel<1><<<dim3(1536 / BN, (m + BM - 1) / BM), 256>>>(
            nullptr, Ws, bs, iou, hbuf, m, 1536, base);
        // child h @ Wf + bf -> [4m, 512]
        gemm_kernel<2><<<dim3(512 / BN, (4 * m + BM - 1) / BM), 256>>>(
            nullptr, Wf, bf, fraw, hbuf, 4 * m, 512, base);
        combine_kernel<<<m, 512>>>(ifou, iou, fraw, cbuf, hbuf, base);
    }

    copyout_kernel<<<1, 512>>>(hbuf, out);
}

// round 2
// speedup vs baseline: 1.7767x; 1.7767x over previous
#include <cuda_runtime.h>
#include <math.h>

#define NN 4096
#define MEM 512

// ---------------- scratch (static device globals; no allocation) ----------------
__device__ float g_ifou[NN * 2048];            // inputs @ Wx + bx
__device__ float g_c[(NN + 1) * MEM];          // cell states, row NN = sentinel zeros
__device__ float g_h[(NN + 1) * MEM];          // hidden states, row NN = sentinel zeros
__device__ float g_iou[683 * 1536];            // per-level hsum @ Ws + bs
__device__ float g_fw[(NN + 1) * MEM];         // per-node h @ Wf + bf (row NN = zeros)

__device__ __forceinline__ float sigmoidf_(float x) { return 1.0f / (1.0f + expf(-x)); }

// children of node p are ids 4p-12289 .. 4p-12286 (clip <0 -> sentinel NN)
__device__ __forceinline__ int child_id(int p, int k) {
    int c = 4 * p - 12289 + k;
    return c < 0 ? NN : c;
}

// =====================================================================
// BM128 GEMM: C[M,Ncol] = A[M,512] @ B[512,Ncol] + bias  (dense A)
// 128x128 tile, BK=8, 256 threads, 8x8 microtile, register prefetch.
// =====================================================================
__global__ __launch_bounds__(256)
void gemm128_kernel(const float* __restrict__ A, const float* __restrict__ B,
                    const float* __restrict__ bias, float* __restrict__ C,
                    int M, int Ncol) {
    __shared__ float As[8][128];
    __shared__ float Bs[8][128];
    const int tid = threadIdx.x;
    const int bm = blockIdx.y * 128;
    const int bn = blockIdx.x * 128;
    const int tx = tid & 15;
    const int ty = tid >> 4;

    float acc[8][8];
#pragma unroll
    for (int i = 0; i < 8; ++i)
#pragma unroll
        for (int j = 0; j < 8; ++j) acc[i][j] = 0.f;

    const int arow = tid >> 1;
    const int akp = (tid & 1) * 4;
    const int bcol = (tid & 31) * 4;
    const int bkrow = tid >> 5;

    const int ar = bm + arow;
    float4 av = (ar < M) ? *reinterpret_cast<const float4*>(A + (size_t)ar * 512 + akp)
                         : make_float4(0.f, 0.f, 0.f, 0.f);
    float4 bv = *reinterpret_cast<const float4*>(B + (size_t)bkrow * Ncol + bn + bcol);

    for (int k0 = 0; k0 < 512; k0 += 8) {
        As[akp + 0][arow] = av.x;
        As[akp + 1][arow] = av.y;
        As[akp + 2][arow] = av.z;
        As[akp + 3][arow] = av.w;
        *reinterpret_cast<float4*>(&Bs[bkrow][bcol]) = bv;
        __syncthreads();
        if (k0 + 8 < 512) {
            av = (ar < M) ? *reinterpret_cast<const float4*>(A + (size_t)ar * 512 + k0 + 8 + akp)
                          : make_float4(0.f, 0.f, 0.f, 0.f);
            bv = *reinterpret_cast<const float4*>(B + (size_t)(k0 + 8 + bkrow) * Ncol + bn + bcol);
        }
#pragma unroll
        for (int kk = 0; kk < 8; ++kk) {
            float a[8], b[8];
            *reinterpret_cast<float4*>(&a[0]) = *reinterpret_cast<const float4*>(&As[kk][ty * 8]);
            *reinterpret_cast<float4*>(&a[4]) = *reinterpret_cast<const float4*>(&As[kk][ty * 8 + 4]);
            *reinterpret_cast<float4*>(&b[0]) = *reinterpret_cast<const float4*>(&Bs[kk][tx * 8]);
            *reinterpret_cast<float4*>(&b[4]) = *reinterpret_cast<const float4*>(&Bs[kk][tx * 8 + 4]);
#pragma unroll
            for (int i = 0; i < 8; ++i)
#pragma unroll
                for (int j = 0; j < 8; ++j) acc[i][j] = fmaf(a[i], b[j], acc[i][j]);
        }
        __syncthreads();
    }

#pragma unroll
    for (int i = 0; i < 8; ++i) {
        int row = bm + ty * 8 + i;
        if (row < M) {
            int col = bn + tx * 8;
            float4 o0, o1;
            o0.x = acc[i][0] + bias[col + 0];
            o0.y = acc[i][1] + bias[col + 1];
            o0.z = acc[i][2] + bias[col + 2];
            o0.w = acc[i][3] + bias[col + 3];
            o1.x = acc[i][4] + bias[col + 4];
            o1.y = acc[i][5] + bias[col + 5];
            o1.z = acc[i][6] + bias[col + 6];
            o1.w = acc[i][7] + bias[col + 7];
            *reinterpret_cast<float4*>(&C[(size_t)row * Ncol + col]) = o0;
            *reinterpret_cast<float4*>(&C[(size_t)row * Ncol + col + 4]) = o1;
        }
    }
}

// =====================================================================
// BM32 GEMM: 32x128 tile, BK=16, 256 threads, 4x4 microtile, prefetch.
// MODE 0: dense A.  MODE 1: A row m = sum of the 4 child h-rows of node pbase+m.
// =====================================================================
template <int MODE>
__device__ __forceinline__ float2 load_a2(const float* __restrict__ A,
                                          const float* __restrict__ H,
                                          int row, int kcol, int M, int pbase) {
    float2 z = make_float2(0.f, 0.f);
    if (row >= M) return z;
    if (MODE == 0) {
        return *reinterpret_cast<const float2*>(A + (size_t)row * 512 + kcol);
    } else {
        int p = pbase + row;
        float2 s = z;
#pragma unroll
        for (int k = 0; k < 4; ++k) {
            int cid = child_id(p, k);
            float2 v = *reinterpret_cast<const float2*>(H + (size_t)cid * 512 + kcol);
            s.x += v.x; s.y += v.y;
        }
        return s;
    }
}

template <int MODE>
__global__ __launch_bounds__(256)
void gemm32_kernel(const float* __restrict__ A, const float* __restrict__ B,
                   const float* __restrict__ bias, float* __restrict__ C,
                   const float* __restrict__ H, int M, int Ncol, int pbase) {
    __shared__ float As[16][32];
    __shared__ float Bs[16][128];
    const int tid = threadIdx.x;
    const int bm = blockIdx.y * 32;
    const int bn = blockIdx.x * 128;

    const int ar = tid & 31;           // A row in tile
    const int ak = (tid >> 5) * 2;     // A k-pair
    const int bc = (tid & 31) * 4;     // B col
    const int bk = tid >> 5;           // B k-row (and +8)
    const int ty = tid >> 5;           // 0..7 -> rows ty*4..+3
    const int tx = tid & 31;           // 0..31 -> cols tx*4..+3

    float acc[4][4];
#pragma unroll
    for (int i = 0; i < 4; ++i)
#pragma unroll
        for (int j = 0; j < 4; ++j) acc[i][j] = 0.f;

    float2 av = load_a2<MODE>(A, H, bm + ar, ak, M, pbase);
    float4 bv0 = *reinterpret_cast<const float4*>(B + (size_t)bk * Ncol + bn + bc);
    float4 bv1 = *reinterpret_cast<const float4*>(B + (size_t)(bk + 8) * Ncol + bn + bc);

    for (int k0 = 0; k0 < 512; k0 += 16) {
        As[ak + 0][ar] = av.x;
        As[ak + 1][ar] = av.y;
        *reinterpret_cast<float4*>(&Bs[bk][bc]) = bv0;
        *reinterpret_cast<float4*>(&Bs[bk + 8][bc]) = bv1;
        __syncthreads();
        if (k0 + 16 < 512) {
            av = load_a2<MODE>(A, H, bm + ar, k0 + 16 + ak, M, pbase);
            bv0 = *reinterpret_cast<const float4*>(B + (size_t)(k0 + 16 + bk) * Ncol + bn + bc);
            bv1 = *reinterpret_cast<const float4*>(B + (size_t)(k0 + 24 + bk) * Ncol + bn + bc);
        }
#pragma unroll
        for (int kk = 0; kk < 16; ++kk) {
            float a[4], b[4];
            *reinterpret_cast<float4*>(&a[0]) = *reinterpret_cast<const float4*>(&As[kk][ty * 4]);
            *reinterpret_cast<float4*>(&b[0]) = *reinterpret_cast<const float4*>(&Bs[kk][tx * 4]);
#pragma unroll
            for (int i = 0; i < 4; ++i)
#pragma unroll
                for (int j = 0; j < 4; ++j) acc[i][j] = fmaf(a[i], b[j], acc[i][j]);
        }
        __syncthreads();
    }

#pragma unroll
    for (int i = 0; i < 4; ++i) {
        int row = bm + ty * 4 + i;
        if (row < M) {
            int col = bn + tx * 4;
            float4 o;
            o.x = acc[i][0] + bias[col + 0];
            o.y = acc[i][1] + bias[col + 1];
            o.z = acc[i][2] + bias[col + 2];
            o.w = acc[i][3] + bias[col + 3];
            *reinterpret_cast<float4*>(&C[(size_t)row * Ncol + col]) = o;
        }
    }
}

// ---------------- elementwise kernels ----------------
__global__ void init_kernel(float* cbuf, float* hbuf, float* fw) {
    int j = threadIdx.x;
    cbuf[(size_t)NN * MEM + j] = 0.f;
    hbuf[(size_t)NN * MEM + j] = 0.f;
    fw[(size_t)NN * MEM + j] = 0.f;
}

// leaves: ids 0..3071, no children -> iou = bs, c = i*u
__global__ void leaf_kernel(const float* __restrict__ ifou, const float* __restrict__ bs,
                            float* __restrict__ cbuf, float* __restrict__ hbuf) {
    int p = blockIdx.x;
    int j = threadIdx.x;
    const float* r = ifou + (size_t)p * 2048;
    float iv = sigmoidf_(r[j] + bs[j]);
    float ov = sigmoidf_(r[1024 + j] + bs[512 + j]);
    float uv = tanhf(r[1536 + j] + bs[1024 + j]);
    float c = iv * uv;
    cbuf[(size_t)p * MEM + j] = c;
    hbuf[(size_t)p * MEM + j] = ov * tanhf(c);
}

// internal node combine: reads per-node fw = h@Wf + bf of children
__global__ void combine_kernel(const float* __restrict__ ifou, const float* __restrict__ iou,
                               const float* __restrict__ fw, float* __restrict__ cbuf,
                               float* __restrict__ hbuf, int base) {
    int m = blockIdx.x;
    int j = threadIdx.x;
    int p = base + m;
    const float* r = ifou + (size_t)p * 2048;
    float ix = r[j], fx = r[512 + j], ox = r[1024 + j], ux = r[1536 + j];
    float iv = sigmoidf_(ix + iou[(size_t)m * 1536 + j]);
    float ov = sigmoidf_(ox + iou[(size_t)m * 1536 + 512 + j]);
    float uv = tanhf(ux + iou[(size_t)m * 1536 + 1024 + j]);
    float c = iv * uv;
#pragma unroll
    for (int k = 0; k < 4; ++k) {
        int cid = child_id(p, k);
        float f = sigmoidf_(fw[(size_t)cid * MEM + j] + fx);
        c += f * cbuf[(size_t)cid * MEM + j];
    }
    cbuf[(size_t)p * MEM + j] = c;
    hbuf[(size_t)p * MEM + j] = ov * tanhf(c);
}

__global__ void copyout_kernel(const float* __restrict__ hbuf, float* __restrict__ out) {
    out[threadIdx.x] = hbuf[(size_t)(NN - 1) * MEM + threadIdx.x];
}

// ---------------- launch ----------------
extern "C" void kernel_launch(void* const* d_in, const int* in_sizes, int n_in,
                              void* d_out, int out_size) {
    const float* inputs = (const float*)d_in[0];   // [4096, 512]
    const float* Wx     = (const float*)d_in[1];   // [512, 2048]
    const float* bx     = (const float*)d_in[2];   // [2048]
    const float* Ws     = (const float*)d_in[3];   // [512, 1536]
    const float* bs     = (const float*)d_in[4];   // [1536]
    const float* Wf     = (const float*)d_in[5];   // [512, 512]
    const float* bf     = (const float*)d_in[6];   // [512]
    float* out = (float*)d_out;                    // [512]

    float *ifou, *cbuf, *hbuf, *iou, *fw;
    cudaGetSymbolAddress((void**)&ifou, g_ifou);
    cudaGetSymbolAddress((void**)&cbuf, g_c);
    cudaGetSymbolAddress((void**)&hbuf, g_h);
    cudaGetSymbolAddress((void**)&iou, g_iou);
    cudaGetSymbolAddress((void**)&fw, g_fw);

    init_kernel<<<1, 512>>>(cbuf, hbuf, fw);

    // ifou = inputs @ Wx + bx for all nodes  (BM128 path: 16x32 = 512 blocks)
    gemm128_kernel<<<dim3(2048 / 128, 4096 / 128), 256>>>(inputs, Wx, bx, ifou, NN, 2048);

    // leaves (ids 0..3071)
    leaf_kernel<<<3072, 512>>>(ifou, bs, cbuf, hbuf);

    // fw for all leaves: [3072,512] @ Wf + bf   (dense, 4x96 = 384 blocks)
    gemm32_kernel<0><<<dim3(512 / 128, 3072 / 32), 256>>>(hbuf, Wf, bf, fw, nullptr, 3072, 512, 0);

    static const int baseArr[6] = {3072, 3755, 4011, 4075, 4091, 4095};
    static const int cntArr[6]  = {683, 256, 64, 16, 4, 1};
    for (int l = 0; l < 6; ++l) {
        int m = cntArr[l], base = baseArr[l];
        // iou = (sum of child h) @ Ws + bs   -> [m, 1536]
        gemm32_kernel<1><<<dim3(1536 / 128, (m + 31) / 32), 256>>>(
            nullptr, Ws, bs, iou, hbuf, m, 1536, base);
        combine_kernel<<<m, 512>>>(ifou, iou, fw, cbuf, hbuf, base);
        if (l < 5) {
            // fw for this level's nodes: h[base..base+m) @ Wf + bf (dense)
            gemm32_kernel<0><<<dim3(512 / 128, (m + 31) / 32), 256>>>(
                hbuf + (size_t)base * 512, Wf, bf, fw + (size_t)base * 512,
                nullptr, m, 512, 0);
        }
    }

    copyout_kernel<<<1, 512>>>(hbuf, out);
}